// round 13
// baseline (speedup 1.0000x reference)
#include <cuda_runtime.h>
#include <cuda_fp16.h>
#include <math.h>
#include <float.h>
#include <stdint.h>

#define NN 256
#define CC 128
#define HH 4
#define DD 32
#define MM (NN*NN)     // 65536
#define HD (HH*DD)     // 128
#define INF_ 1e9f
#define LN_EPS 1e-5f

// ---- scratch ----
__device__ uint32_t g_xn32[MM*CC/2];     // xn half2-packed along C
__device__ uint32_t g_q32 [MM*HD/2];     // q half, scale applied
__device__ uint32_t g_k32 [MM*HD/2];     // k half
__device__ uint32_t g_vt32[MM*HD/2];     // v half, layout [I][h][d][key]
__device__ uint32_t g_g32 [MM*HD/2];     // gate pre-sigmoid, half2
__device__ uint32_t g_o32 [MM*HD/2];     // attn out (normalized), half2
__device__ uint32_t g_tbt16[HH*NN*NN/2]; // [h][j][k/2] half2
__device__ uint32_t g_wp32[4*HD*CC/2];   // [wi][n][kp]
__device__ uint32_t g_wop32[CC*HD/2];    // [n][kp]

// ---------------------------------------------------------------
__device__ __forceinline__ uint32_t pack_h2(float lo, float hi) {
    __half2 h = __floats2half2_rn(lo, hi);
    return *(uint32_t*)&h;
}
__device__ __forceinline__ float2 unpack_h2(uint32_t w) {
    __half2 h = *(__half2*)&w;
    return __half22float2(h);
}

__device__ __forceinline__ void mma_f16(float c[4], const uint32_t a[4],
                                        uint32_t b0, uint32_t b1) {
    asm volatile(
        "mma.sync.aligned.m16n8k16.row.col.f32.f16.f16.f32 "
        "{%0,%1,%2,%3}, {%4,%5,%6,%7}, {%8,%9}, {%0,%1,%2,%3};\n"
        : "+f"(c[0]), "+f"(c[1]), "+f"(c[2]), "+f"(c[3])
        : "r"(a[0]), "r"(a[1]), "r"(a[2]), "r"(a[3]), "r"(b0), "r"(b1));
}

__device__ __forceinline__ void ldsm_x4(uint32_t& r0, uint32_t& r1,
                                        uint32_t& r2, uint32_t& r3, uint32_t addr) {
    asm volatile("ldmatrix.sync.aligned.m8n8.x4.shared.b16 {%0,%1,%2,%3}, [%4];"
                 : "=r"(r0), "=r"(r1), "=r"(r2), "=r"(r3) : "r"(addr));
}

// ---------------------------------------------------------------
// Kernel 0: pack weights to half2
// ---------------------------------------------------------------
__global__ void prep_weights(const float* __restrict__ wq, const float* __restrict__ wk,
                             const float* __restrict__ wv, const float* __restrict__ wg,
                             const float* __restrict__ wo)
{
    int idx = blockIdx.x * 256 + threadIdx.x;
    if (idx < 4*HD*CC/2) {
        int wi = idx >> 13;
        int rem = idx & 8191;
        int n = rem >> 6, kp = rem & 63;
        const float* W = (wi == 0) ? wq : (wi == 1) ? wk : (wi == 2) ? wv : wg;
        g_wp32[idx] = pack_h2(W[(2*kp)*HD + n], W[(2*kp + 1)*HD + n]);
    } else {
        int r = idx - 4*HD*CC/2;
        int n = r >> 6, kp = r & 63;
        g_wop32[r] = pack_h2(wo[n*HD + 2*kp], wo[n*HD + 2*kp + 1]);
    }
}

// ---------------------------------------------------------------
// Kernel 1: LayerNorm (warp per row) + triangle-bias dots
// ---------------------------------------------------------------
__global__ __launch_bounds__(256)
void ln_kernel(const float* __restrict__ x,
               const float* __restrict__ ln_w,
               const float* __restrict__ ln_b,
               const float* __restrict__ w_bias)
{
    int warp = threadIdx.x >> 5, lane = threadIdx.x & 31;
    int m  = blockIdx.x * 8 + warp;
    int i1 = m >> 8;
    int i2 = m & 255;

    float4 v4 = *(const float4*)&x[(i2*NN + i1)*CC + lane*4];

    float s = v4.x + v4.y + v4.z + v4.w;
    #pragma unroll
    for (int o = 16; o > 0; o >>= 1) s += __shfl_xor_sync(0xffffffffu, s, o);
    float mu = s * (1.0f / CC);

    float dx = v4.x - mu, dy = v4.y - mu, dz = v4.z - mu, dw = v4.w - mu;
    float s2 = dx*dx + dy*dy + dz*dz + dw*dw;
    #pragma unroll
    for (int o = 16; o > 0; o >>= 1) s2 += __shfl_xor_sync(0xffffffffu, s2, o);
    float rs = rsqrtf(s2 * (1.0f / CC) + LN_EPS);

    float4 w4 = *(const float4*)&ln_w[lane*4];
    float4 b4 = *(const float4*)&ln_b[lane*4];
    float xn0 = dx*rs*w4.x + b4.x;
    float xn1 = dy*rs*w4.y + b4.y;
    float xn2 = dz*rs*w4.z + b4.z;
    float xn3 = dw*rs*w4.w + b4.w;

    *(uint2*)&g_xn32[m*(CC/2) + lane*2] =
        make_uint2(pack_h2(xn0, xn1), pack_h2(xn2, xn3));

    // triangle bias dots; layout [h][j=i1][k=i2], half storage
    float acc[4];
    #pragma unroll
    for (int h = 0; h < 4; h++) {
        float4 wb = *(const float4*)&w_bias[h*CC + lane*4];
        acc[h] = xn0*wb.x + xn1*wb.y + xn2*wb.z + xn3*wb.w;
    }
    #pragma unroll
    for (int o = 16; o > 0; o >>= 1) {
        #pragma unroll
        for (int h = 0; h < 4; h++)
            acc[h] += __shfl_xor_sync(0xffffffffu, acc[h], o);
    }
    if (lane < 4)
        ((__half*)g_tbt16)[(lane*NN + i1)*NN + i2] = __float2half_rn(acc[lane]);
}

// ---------------------------------------------------------------
// Kernel 2: FUSED q/k/v/g projections. grid 512. As loaded once,
// loop over the 4 weight matrices.
// ---------------------------------------------------------------
#define TS_STR 68
#define TS_SZ (128*TS_STR)
#define GEMM_SMEM (2*TS_SZ*4)     // 69632 B

__global__ __launch_bounds__(256, 2)
void gemm_proj_f16()
{
    extern __shared__ uint32_t ts[];
    uint32_t* As = ts;
    uint32_t* Bs = ts + TS_SZ;

    int m0 = blockIdx.x * 128;

    int tid = threadIdx.x;
    int warp = tid >> 5, lane = tid & 31;
    int g = lane >> 2, t = lane & 3;
    int wm = warp >> 2, wn = warp & 3;
    int mbase = wm*64, nbase = wn*32;

    // load A once
    #pragma unroll
    for (int i = 0; i < 8; i++) {
        int f = tid + 256*i;
        int r = f >> 4, q4 = (f & 15) * 4;
        *(uint4*)&As[r*TS_STR + q4] = *(const uint4*)&g_xn32[(m0 + r)*(CC/2) + q4];
    }

    for (int wi = 0; wi < 4; wi++) {
        const uint32_t* wp = g_wp32 + wi*HD*(CC/2);
        __syncthreads();   // Bs free (and As ready on first iter)
        #pragma unroll
        for (int i = 0; i < 8; i++) {
            int f = tid + 256*i;
            int r = f >> 4, q4 = (f & 15) * 4;
            *(uint4*)&Bs[r*TS_STR + q4] = *(const uint4*)&wp[r*(CC/2) + q4];
        }
        __syncthreads();

        float osc = (wi == 0) ? 0.17677669529663689f : 1.0f;
        float acc[4][4][4] = {};

        #pragma unroll
        for (int ks = 0; ks < 8; ks++) {
            uint32_t af[4][4];
            #pragma unroll
            for (int mt = 0; mt < 4; mt++) {
                int r0 = mbase + mt*16 + g;
                af[mt][0] = As[ r0     *TS_STR + ks*8 + t    ];
                af[mt][1] = As[(r0 + 8)*TS_STR + ks*8 + t    ];
                af[mt][2] = As[ r0     *TS_STR + ks*8 + t + 4];
                af[mt][3] = As[(r0 + 8)*TS_STR + ks*8 + t + 4];
            }
            uint32_t bf0[4], bf1[4];
            #pragma unroll
            for (int nt = 0; nt < 4; nt++) {
                int nc = nbase + nt*8 + g;
                bf0[nt] = Bs[nc*TS_STR + ks*8 + t    ];
                bf1[nt] = Bs[nc*TS_STR + ks*8 + t + 4];
            }
            #pragma unroll
            for (int mt = 0; mt < 4; mt++)
                #pragma unroll
                for (int nt = 0; nt < 4; nt++)
                    mma_f16(acc[mt][nt], af[mt], bf0[nt], bf1[nt]);
        }

        #pragma unroll
        for (int mt = 0; mt < 4; mt++) {
            int row0 = m0 + mbase + mt*16 + g;
            int row1 = row0 + 8;
            #pragma unroll
            for (int nt = 0; nt < 4; nt++) {
                int ncol = nbase + nt*8 + 2*t;
                float c00 = acc[mt][nt][0]*osc, c01 = acc[mt][nt][1]*osc;
                float c10 = acc[mt][nt][2]*osc, c11 = acc[mt][nt][3]*osc;
                if (wi == 0) {
                    g_q32[row0*(HD/2) + (ncol >> 1)] = pack_h2(c00, c01);
                    g_q32[row1*(HD/2) + (ncol >> 1)] = pack_h2(c10, c11);
                } else if (wi == 1) {
                    g_k32[row0*(HD/2) + (ncol >> 1)] = pack_h2(c00, c01);
                    g_k32[row1*(HD/2) + (ncol >> 1)] = pack_h2(c10, c11);
                } else if (wi == 2) {
                    __half* vt = (__half*)g_vt32;
                    int h = ncol >> 5, d = ncol & 31;
                    int I0 = row0 >> 8, key0 = row0 & 255;
                    int I1 = row1 >> 8, key1 = row1 & 255;
                    vt[((I0*HH + h)*DD + d    )*NN + key0] = __float2half_rn(c00);
                    vt[((I0*HH + h)*DD + d + 1)*NN + key0] = __float2half_rn(c01);
                    vt[((I1*HH + h)*DD + d    )*NN + key1] = __float2half_rn(c10);
                    vt[((I1*HH + h)*DD + d + 1)*NN + key1] = __float2half_rn(c11);
                } else {
                    g_g32[row0*(HD/2) + (ncol >> 1)] = pack_h2(c00, c01);
                    g_g32[row1*(HD/2) + (ncol >> 1)] = pack_h2(c10, c11);
                }
            }
        }
    }
}

// ---------------------------------------------------------------
// Kernel 3: f16 mma flash attention (ldmatrix), half2 triangle bias.
// ---------------------------------------------------------------
#define KSH_STR 20
#define VT_STR 132
#define ATTN_SMEM ((NN*KSH_STR + DD*VT_STR + NN) * 4)   // 38400 B

__global__ __launch_bounds__(256, 2)
void attn_f16(const float* __restrict__ mask)
{
    extern __shared__ uint32_t sm32[];
    uint32_t* Ksh = sm32;                       // [256][20]
    uint32_t* Vt  = sm32 + NN*KSH_STR;          // [32][132]
    float*    mb  = (float*)(sm32 + NN*KSH_STR + DD*VT_STR); // [256]

    int I = blockIdx.x, h = blockIdx.y;
    int tid  = threadIdx.x;
    int warp = tid >> 5, lane = tid & 31;
    int g = lane >> 2, t = lane & 3;

    #pragma unroll
    for (int i = 0; i < 16; i++) {
        int idx = tid + 256*i;
        int key = idx >> 4, w = idx & 15;
        Ksh[key*KSH_STR + w] = g_k32[(size_t)(I*NN + key)*(HD/2) + h*16 + w];
    }
    {
        const uint32_t* vsrc = g_vt32 + (size_t)(I*HH + h)*DD*(NN/2);
        #pragma unroll
        for (int i = 0; i < 16; i++) {
            int idx = tid + 256*i;
            int d = idx >> 7, w = idx & 127;
            Vt[d*VT_STR + w] = vsrc[d*(NN/2) + w];
        }
    }
    mb[tid] = INF_ * (mask[tid*NN + I] - 1.0f);

    int q0 = warp * 32;
    const uint32_t* qbase = g_q32 + (size_t)(I*NN)*(HD/2) + h*16;
    uint32_t aq[2][2][4];
    #pragma unroll
    for (int mt = 0; mt < 2; mt++)
        #pragma unroll
        for (int ks = 0; ks < 2; ks++) {
            int r0 = q0 + mt*16 + g;
            aq[mt][ks][0] = qbase[(size_t) r0     *(HD/2) + ks*8 + t    ];
            aq[mt][ks][1] = qbase[(size_t)(r0 + 8)*(HD/2) + ks*8 + t    ];
            aq[mt][ks][2] = qbase[(size_t) r0     *(HD/2) + ks*8 + t + 4];
            aq[mt][ks][3] = qbase[(size_t)(r0 + 8)*(HD/2) + ks*8 + t + 4];
        }

    int sel = lane >> 3;
    uint32_t ksh_u = (uint32_t)__cvta_generic_to_shared(Ksh);
    uint32_t vt_u  = (uint32_t)__cvta_generic_to_shared(Vt);
    uint32_t kaddr = ksh_u + ((((sel >> 1)*8 + (lane & 7))*KSH_STR) + (sel & 1)*4) * 4;
    uint32_t vaddr = vt_u + (((sel >> 1)*8 + (lane & 7))*VT_STR) * 4 + (sel & 1)*16;

    float Of[2][4][4] = {};
    float lacc[2][2] = {};

    const uint32_t* tbp = g_tbt16 + h*NN*(NN/2);   // [j][k/2] half2

    __syncthreads();

    for (int kc = 0; kc < NN; kc += 32) {
        // ---- S = Q K^T ----
        float S[2][4][4] = {};
        #pragma unroll
        for (int ks = 0; ks < 2; ks++) {
            uint32_t b0[4], b1[4];
            ldsm_x4(b0[0], b1[0], b0[1], b1[1],
                    kaddr + ( kc      *KSH_STR + ks*8) * 4);
            ldsm_x4(b0[2], b1[2], b0[3], b1[3],
                    kaddr + ((kc + 16)*KSH_STR + ks*8) * 4);
            #pragma unroll
            for (int nt = 0; nt < 4; nt++) {
                mma_f16(S[0][nt], aq[0][ks], b0[nt], b1[nt]);
                mma_f16(S[1][nt], aq[1][ks], b0[nt], b1[nt]);
            }
        }
        // ---- biases + exp + row sums ----
        #pragma unroll
        for (int nt = 0; nt < 4; nt++) {
            int kcol = kc + nt*8 + t*2;
            int kw = kcol >> 1;
            float2 mbv = *(const float2*)&mb[kcol];
            #pragma unroll
            for (int mt = 0; mt < 2; mt++) {
                int row0 = q0 + mt*16 + g;
                float2 t0 = unpack_h2(tbp[ row0     *(NN/2) + kw]);
                float2 t1 = unpack_h2(tbp[(row0 + 8)*(NN/2) + kw]);
                float p0 = __expf(S[mt][nt][0] + mbv.x + t0.x);
                float p1 = __expf(S[mt][nt][1] + mbv.y + t0.y);
                float p2 = __expf(S[mt][nt][2] + mbv.x + t1.x);
                float p3 = __expf(S[mt][nt][3] + mbv.y + t1.y);
                S[mt][nt][0] = p0; S[mt][nt][1] = p1;
                S[mt][nt][2] = p2; S[mt][nt][3] = p3;
                lacc[mt][0] += p0 + p1;
                lacc[mt][1] += p2 + p3;
            }
        }
        // ---- O += P V ----
        #pragma unroll
        for (int kh = 0; kh < 2; kh++) {
            int kcp = (kc >> 1) + kh*8;
            uint32_t bv0[4], bv1[4];
            ldsm_x4(bv0[0], bv1[0], bv0[1], bv1[1], vaddr + kcp*4);
            ldsm_x4(bv0[2], bv1[2], bv0[3], bv1[3], vaddr + (16*VT_STR + kcp)*4);
            #pragma unroll
            for (int mt = 0; mt < 2; mt++) {
                uint32_t ap[4];
                ap[0] = pack_h2(S[mt][kh*2  ][0], S[mt][kh*2  ][1]);
                ap[1] = pack_h2(S[mt][kh*2  ][2], S[mt][kh*2  ][3]);
                ap[2] = pack_h2(S[mt][kh*2+1][0], S[mt][kh*2+1][1]);
                ap[3] = pack_h2(S[mt][kh*2+1][2], S[mt][kh*2+1][3]);
                #pragma unroll
                for (int ntd = 0; ntd < 4; ntd++)
                    mma_f16(Of[mt][ntd], ap, bv0[ntd], bv1[ntd]);
            }
        }
    }

    // ---- epilogue ----
    uint32_t* obase = g_o32 + (size_t)(I*NN)*(HD/2) + h*16;
    #pragma unroll
    for (int mt = 0; mt < 2; mt++) {
        float l0 = lacc[mt][0];
        l0 += __shfl_xor_sync(0xffffffffu, l0, 1);
        l0 += __shfl_xor_sync(0xffffffffu, l0, 2);
        float l1 = lacc[mt][1];
        l1 += __shfl_xor_sync(0xffffffffu, l1, 1);
        l1 += __shfl_xor_sync(0xffffffffu, l1, 2);
        float inv0 = 1.0f / l0;
        float inv1 = 1.0f / l1;
        int row0 = q0 + mt*16 + g;
        int row1 = row0 + 8;
        #pragma unroll
        for (int ntd = 0; ntd < 4; ntd++) {
            int wp = ntd*4 + t;
            obase[(size_t)row0*(HD/2) + wp] = pack_h2(Of[mt][ntd][0]*inv0, Of[mt][ntd][1]*inv0);
            obase[(size_t)row1*(HD/2) + wp] = pack_h2(Of[mt][ntd][2]*inv1, Of[mt][ntd][3]*inv1);
        }
    }
}

// ---------------------------------------------------------------
// Kernel 4: gated output projection, f16 mma + scatter epilogue
// ---------------------------------------------------------------
__global__ __launch_bounds__(256, 2)
void gemm_out_f16(const float* __restrict__ bg, const float* __restrict__ bo,
                  float* __restrict__ out)
{
    extern __shared__ uint32_t ts[];
    uint32_t* As = ts;
    uint32_t* Bs = ts + TS_SZ;

    int m0 = blockIdx.x * 128;

    int tid = threadIdx.x;
    int warp = tid >> 5, lane = tid & 31;
    int g = lane >> 2, t = lane & 3;
    int wm = warp >> 2, wn = warp & 3;
    int mbase = wm*64, nbase = wn*32;

    #pragma unroll
    for (int i = 0; i < 16; i++) {
        int s = tid + 256*i;
        int r = s >> 5, wp = (s & 31) * 2;
        uint2 o2 = *(const uint2*)&g_o32[(size_t)(m0 + r)*(HD/2) + wp];
        uint2 g2 = *(const uint2*)&g_g32[(size_t)(m0 + r)*(HD/2) + wp];
        float4 bg4 = *(const float4*)&bg[wp*2];
        float2 oa = unpack_h2(o2.x), ob = unpack_h2(o2.y);
        float2 ga = unpack_h2(g2.x), gb = unpack_h2(g2.y);
        float a0 = oa.x / (1.0f + __expf(-(ga.x + bg4.x)));
        float a1 = oa.y / (1.0f + __expf(-(ga.y + bg4.y)));
        float a2 = ob.x / (1.0f + __expf(-(gb.x + bg4.z)));
        float a3 = ob.y / (1.0f + __expf(-(gb.y + bg4.w)));
        As[r*TS_STR + wp    ] = pack_h2(a0, a1);
        As[r*TS_STR + wp + 1] = pack_h2(a2, a3);
    }
    #pragma unroll
    for (int i = 0; i < 8; i++) {
        int f = tid + 256*i;
        int n = f >> 4, kp4 = (f & 15) * 4;
        *(uint4*)&Bs[n*TS_STR + kp4] = *(const uint4*)&g_wop32[n*(HD/2) + kp4];
    }
    __syncthreads();

    float acc[4][4][4] = {};

    #pragma unroll
    for (int ks = 0; ks < 8; ks++) {
        uint32_t af[4][4];
        #pragma unroll
        for (int mt = 0; mt < 4; mt++) {
            int r0 = mbase + mt*16 + g;
            af[mt][0] = As[ r0     *TS_STR + ks*8 + t    ];
            af[mt][1] = As[(r0 + 8)*TS_STR + ks*8 + t    ];
            af[mt][2] = As[ r0     *TS_STR + ks*8 + t + 4];
            af[mt][3] = As[(r0 + 8)*TS_STR + ks*8 + t + 4];
        }
        uint32_t bf0[4], bf1[4];
        #pragma unroll
        for (int nt = 0; nt < 4; nt++) {
            int nc = nbase + nt*8 + g;
            bf0[nt] = Bs[nc*TS_STR + ks*8 + t    ];
            bf1[nt] = Bs[nc*TS_STR + ks*8 + t + 4];
        }
        #pragma unroll
        for (int mt = 0; mt < 4; mt++)
            #pragma unroll
            for (int nt = 0; nt < 4; nt++)
                mma_f16(acc[mt][nt], af[mt], bf0[nt], bf1[nt]);
    }

    #pragma unroll
    for (int mt = 0; mt < 4; mt++) {
        int mr0 = m0 + mbase + mt*16 + g;
        int mr1 = mr0 + 8;
        int or0 = (mr0 & 255)*NN + (mr0 >> 8);
        int or1 = (mr1 & 255)*NN + (mr1 >> 8);
        #pragma unroll
        for (int nt = 0; nt < 4; nt++) {
            int col = nbase + nt*8 + 2*t;
            float2 b2 = *(const float2*)&bo[col];
            float2 w0 = make_float2(acc[mt][nt][0] + b2.x, acc[mt][nt][1] + b2.y);
            float2 w1 = make_float2(acc[mt][nt][2] + b2.x, acc[mt][nt][3] + b2.y);
            *(float2*)&out[or0*CC + col] = w0;
            *(float2*)&out[or1*CC + col] = w1;
        }
    }
}

// ---------------------------------------------------------------
extern "C" void kernel_launch(void* const* d_in, const int* in_sizes, int n_in,
                              void* d_out, int out_size)
{
    const float* x      = (const float*)d_in[0];
    const float* mask   = (const float*)d_in[1];
    const float* ln_w   = (const float*)d_in[2];
    const float* ln_b   = (const float*)d_in[3];
    const float* w_bias = (const float*)d_in[4];
    const float* wq     = (const float*)d_in[5];
    const float* wk     = (const float*)d_in[6];
    const float* wv     = (const float*)d_in[7];
    const float* wg     = (const float*)d_in[8];
    const float* bg     = (const float*)d_in[9];
    const float* wo     = (const float*)d_in[10];
    const float* bo     = (const float*)d_in[11];
    float* out = (float*)d_out;

    static bool attr_set = false;
    if (!attr_set) {
        cudaFuncSetAttribute(attn_f16, cudaFuncAttributeMaxDynamicSharedMemorySize,
                             ATTN_SMEM);
        cudaFuncSetAttribute(gemm_proj_f16, cudaFuncAttributeMaxDynamicSharedMemorySize,
                             GEMM_SMEM);
        cudaFuncSetAttribute(gemm_out_f16, cudaFuncAttributeMaxDynamicSharedMemorySize,
                             GEMM_SMEM);
        attr_set = true;
    }

    prep_weights<<<160, 256>>>(wq, wk, wv, wg, wo);
    ln_kernel<<<MM/8, 256>>>(x, ln_w, ln_b, w_bias);
    gemm_proj_f16<<<MM/128, 256, GEMM_SMEM>>>();
    attn_f16<<<dim3(NN, HH), 256, ATTN_SMEM>>>(mask);
    gemm_out_f16<<<dim3(MM/128, 1), 256, GEMM_SMEM>>>(bg, bo, out);
}

// round 14
// speedup vs baseline: 1.1010x; 1.1010x over previous
#include <cuda_runtime.h>
#include <cuda_fp16.h>
#include <math.h>
#include <float.h>
#include <stdint.h>

#define NN 256
#define CC 128
#define HH 4
#define DD 32
#define MM (NN*NN)     // 65536
#define HD (HH*DD)     // 128
#define INF_ 1e9f
#define LN_EPS 1e-5f

// ---- scratch ----
__device__ uint32_t g_xn32[MM*CC/2];     // xn half2-packed along C
__device__ uint32_t g_q32 [MM*HD/2];     // q half, scale applied
__device__ uint32_t g_k32 [MM*HD/2];     // k half
__device__ uint32_t g_vt32[MM*HD/2];     // v half, layout [I][h][d][key]
__device__ uint32_t g_g32 [MM*HD/2];     // gate pre-sigmoid, half2
__device__ uint32_t g_o32 [MM*HD/2];     // attn out, normalized AND gated, half2
__device__ uint32_t g_tbt16[HH*NN*NN/2]; // [h][j][k/2] half2
__device__ uint32_t g_wp32[4*HD*CC/2];   // [wi][n][kp]
__device__ uint32_t g_wop32[CC*HD/2];    // [n][kp]

// ---------------------------------------------------------------
__device__ __forceinline__ uint32_t pack_h2(float lo, float hi) {
    __half2 h = __floats2half2_rn(lo, hi);
    return *(uint32_t*)&h;
}
__device__ __forceinline__ float2 unpack_h2(uint32_t w) {
    __half2 h = *(__half2*)&w;
    return __half22float2(h);
}

__device__ __forceinline__ void mma_f16(float c[4], const uint32_t a[4],
                                        uint32_t b0, uint32_t b1) {
    asm volatile(
        "mma.sync.aligned.m16n8k16.row.col.f32.f16.f16.f32 "
        "{%0,%1,%2,%3}, {%4,%5,%6,%7}, {%8,%9}, {%0,%1,%2,%3};\n"
        : "+f"(c[0]), "+f"(c[1]), "+f"(c[2]), "+f"(c[3])
        : "r"(a[0]), "r"(a[1]), "r"(a[2]), "r"(a[3]), "r"(b0), "r"(b1));
}

__device__ __forceinline__ void ldsm_x4(uint32_t& r0, uint32_t& r1,
                                        uint32_t& r2, uint32_t& r3, uint32_t addr) {
    asm volatile("ldmatrix.sync.aligned.m8n8.x4.shared.b16 {%0,%1,%2,%3}, [%4];"
                 : "=r"(r0), "=r"(r1), "=r"(r2), "=r"(r3) : "r"(addr));
}

// ---------------------------------------------------------------
// Kernel 0: pack weights to half2
// ---------------------------------------------------------------
__global__ void prep_weights(const float* __restrict__ wq, const float* __restrict__ wk,
                             const float* __restrict__ wv, const float* __restrict__ wg,
                             const float* __restrict__ wo)
{
    int idx = blockIdx.x * 256 + threadIdx.x;
    if (idx < 4*HD*CC/2) {
        int wi = idx >> 13;
        int rem = idx & 8191;
        int n = rem >> 6, kp = rem & 63;
        const float* W = (wi == 0) ? wq : (wi == 1) ? wk : (wi == 2) ? wv : wg;
        g_wp32[idx] = pack_h2(W[(2*kp)*HD + n], W[(2*kp + 1)*HD + n]);
    } else {
        int r = idx - 4*HD*CC/2;
        int n = r >> 6, kp = r & 63;
        g_wop32[r] = pack_h2(wo[n*HD + 2*kp], wo[n*HD + 2*kp + 1]);
    }
}

// ---------------------------------------------------------------
// Kernel 1: LayerNorm (warp per row) + triangle-bias dots
// ---------------------------------------------------------------
__global__ __launch_bounds__(256)
void ln_kernel(const float* __restrict__ x,
               const float* __restrict__ ln_w,
               const float* __restrict__ ln_b,
               const float* __restrict__ w_bias)
{
    int warp = threadIdx.x >> 5, lane = threadIdx.x & 31;
    int m  = blockIdx.x * 8 + warp;
    int i1 = m >> 8;
    int i2 = m & 255;

    float4 v4 = *(const float4*)&x[(i2*NN + i1)*CC + lane*4];

    float s = v4.x + v4.y + v4.z + v4.w;
    #pragma unroll
    for (int o = 16; o > 0; o >>= 1) s += __shfl_xor_sync(0xffffffffu, s, o);
    float mu = s * (1.0f / CC);

    float dx = v4.x - mu, dy = v4.y - mu, dz = v4.z - mu, dw = v4.w - mu;
    float s2 = dx*dx + dy*dy + dz*dz + dw*dw;
    #pragma unroll
    for (int o = 16; o > 0; o >>= 1) s2 += __shfl_xor_sync(0xffffffffu, s2, o);
    float rs = rsqrtf(s2 * (1.0f / CC) + LN_EPS);

    float4 w4 = *(const float4*)&ln_w[lane*4];
    float4 b4 = *(const float4*)&ln_b[lane*4];
    float xn0 = dx*rs*w4.x + b4.x;
    float xn1 = dy*rs*w4.y + b4.y;
    float xn2 = dz*rs*w4.z + b4.z;
    float xn3 = dw*rs*w4.w + b4.w;

    *(uint2*)&g_xn32[m*(CC/2) + lane*2] =
        make_uint2(pack_h2(xn0, xn1), pack_h2(xn2, xn3));

    // triangle bias dots; layout [h][j=i1][k=i2], half storage
    float acc[4];
    #pragma unroll
    for (int h = 0; h < 4; h++) {
        float4 wb = *(const float4*)&w_bias[h*CC + lane*4];
        acc[h] = xn0*wb.x + xn1*wb.y + xn2*wb.z + xn3*wb.w;
    }
    #pragma unroll
    for (int o = 16; o > 0; o >>= 1) {
        #pragma unroll
        for (int h = 0; h < 4; h++)
            acc[h] += __shfl_xor_sync(0xffffffffu, acc[h], o);
    }
    if (lane < 4)
        ((__half*)g_tbt16)[(lane*NN + i1)*NN + i2] = __float2half_rn(acc[lane]);
}

// ---------------------------------------------------------------
// Kernel 2: q/k/v/g projections, f16 mma, grid (512, 4)
// ---------------------------------------------------------------
#define TS_STR 68
#define TS_SZ (128*TS_STR)
#define GEMM_SMEM (2*TS_SZ*4)     // 69632 B

__global__ __launch_bounds__(256, 2)
void gemm_proj_f16()
{
    extern __shared__ uint32_t ts[];
    uint32_t* As = ts;
    uint32_t* Bs = ts + TS_SZ;

    int wi = blockIdx.y;
    int m0 = blockIdx.x * 128;
    float osc = (wi == 0) ? 0.17677669529663689f : 1.0f;

    int tid = threadIdx.x;
    int warp = tid >> 5, lane = tid & 31;
    int g = lane >> 2, t = lane & 3;
    int wm = warp >> 2, wn = warp & 3;
    int mbase = wm*64, nbase = wn*32;

    const uint32_t* wp = g_wp32 + wi*HD*(CC/2);
    #pragma unroll
    for (int i = 0; i < 8; i++) {
        int f = tid + 256*i;
        int r = f >> 4, q4 = (f & 15) * 4;
        *(uint4*)&As[r*TS_STR + q4] = *(const uint4*)&g_xn32[(m0 + r)*(CC/2) + q4];
        *(uint4*)&Bs[r*TS_STR + q4] = *(const uint4*)&wp[r*(CC/2) + q4];
    }
    __syncthreads();

    float acc[4][4][4] = {};

    #pragma unroll
    for (int ks = 0; ks < 8; ks++) {
        uint32_t af[4][4];
        #pragma unroll
        for (int mt = 0; mt < 4; mt++) {
            int r0 = mbase + mt*16 + g;
            af[mt][0] = As[ r0     *TS_STR + ks*8 + t    ];
            af[mt][1] = As[(r0 + 8)*TS_STR + ks*8 + t    ];
            af[mt][2] = As[ r0     *TS_STR + ks*8 + t + 4];
            af[mt][3] = As[(r0 + 8)*TS_STR + ks*8 + t + 4];
        }
        uint32_t bf0[4], bf1[4];
        #pragma unroll
        for (int nt = 0; nt < 4; nt++) {
            int nc = nbase + nt*8 + g;
            bf0[nt] = Bs[nc*TS_STR + ks*8 + t    ];
            bf1[nt] = Bs[nc*TS_STR + ks*8 + t + 4];
        }
        #pragma unroll
        for (int mt = 0; mt < 4; mt++)
            #pragma unroll
            for (int nt = 0; nt < 4; nt++)
                mma_f16(acc[mt][nt], af[mt], bf0[nt], bf1[nt]);
    }

    #pragma unroll
    for (int mt = 0; mt < 4; mt++) {
        int row0 = m0 + mbase + mt*16 + g;
        int row1 = row0 + 8;
        #pragma unroll
        for (int nt = 0; nt < 4; nt++) {
            int ncol = nbase + nt*8 + 2*t;
            float c00 = acc[mt][nt][0]*osc, c01 = acc[mt][nt][1]*osc;
            float c10 = acc[mt][nt][2]*osc, c11 = acc[mt][nt][3]*osc;
            if (wi == 0) {
                g_q32[row0*(HD/2) + (ncol >> 1)] = pack_h2(c00, c01);
                g_q32[row1*(HD/2) + (ncol >> 1)] = pack_h2(c10, c11);
            } else if (wi == 1) {
                g_k32[row0*(HD/2) + (ncol >> 1)] = pack_h2(c00, c01);
                g_k32[row1*(HD/2) + (ncol >> 1)] = pack_h2(c10, c11);
            } else if (wi == 2) {
                __half* vt = (__half*)g_vt32;
                int h = ncol >> 5, d = ncol & 31;
                int I0 = row0 >> 8, key0 = row0 & 255;
                int I1 = row1 >> 8, key1 = row1 & 255;
                vt[((I0*HH + h)*DD + d    )*NN + key0] = __float2half_rn(c00);
                vt[((I0*HH + h)*DD + d + 1)*NN + key0] = __float2half_rn(c01);
                vt[((I1*HH + h)*DD + d    )*NN + key1] = __float2half_rn(c10);
                vt[((I1*HH + h)*DD + d + 1)*NN + key1] = __float2half_rn(c11);
            } else {
                g_g32[row0*(HD/2) + (ncol >> 1)] = pack_h2(c00, c01);
                g_g32[row1*(HD/2) + (ncol >> 1)] = pack_h2(c10, c11);
            }
        }
    }
}

// ---------------------------------------------------------------
// Kernel 3: f16 mma flash attention (ldmatrix), half2 triangle bias,
// gating fused into the epilogue (stores gated, normalized o).
// ---------------------------------------------------------------
#define KSH_STR 20
#define VT_STR 132
#define ATTN_SMEM ((NN*KSH_STR + DD*VT_STR + NN) * 4)   // 38400 B

__global__ __launch_bounds__(256, 2)
void attn_f16(const float* __restrict__ mask, const float* __restrict__ bg)
{
    extern __shared__ uint32_t sm32[];
    uint32_t* Ksh = sm32;                       // [256][20]
    uint32_t* Vt  = sm32 + NN*KSH_STR;          // [32][132]
    float*    mb  = (float*)(sm32 + NN*KSH_STR + DD*VT_STR); // [256]

    int I = blockIdx.x, h = blockIdx.y;
    int tid  = threadIdx.x;
    int warp = tid >> 5, lane = tid & 31;
    int g = lane >> 2, t = lane & 3;

    #pragma unroll
    for (int i = 0; i < 16; i++) {
        int idx = tid + 256*i;
        int key = idx >> 4, w = idx & 15;
        Ksh[key*KSH_STR + w] = g_k32[(size_t)(I*NN + key)*(HD/2) + h*16 + w];
    }
    {
        const uint32_t* vsrc = g_vt32 + (size_t)(I*HH + h)*DD*(NN/2);
        #pragma unroll
        for (int i = 0; i < 16; i++) {
            int idx = tid + 256*i;
            int d = idx >> 7, w = idx & 127;
            Vt[d*VT_STR + w] = vsrc[d*(NN/2) + w];
        }
    }
    mb[tid] = INF_ * (mask[tid*NN + I] - 1.0f);

    int q0 = warp * 32;
    const uint32_t* qbase = g_q32 + (size_t)(I*NN)*(HD/2) + h*16;
    uint32_t aq[2][2][4];
    #pragma unroll
    for (int mt = 0; mt < 2; mt++)
        #pragma unroll
        for (int ks = 0; ks < 2; ks++) {
            int r0 = q0 + mt*16 + g;
            aq[mt][ks][0] = qbase[(size_t) r0     *(HD/2) + ks*8 + t    ];
            aq[mt][ks][1] = qbase[(size_t)(r0 + 8)*(HD/2) + ks*8 + t    ];
            aq[mt][ks][2] = qbase[(size_t) r0     *(HD/2) + ks*8 + t + 4];
            aq[mt][ks][3] = qbase[(size_t)(r0 + 8)*(HD/2) + ks*8 + t + 4];
        }

    int sel = lane >> 3;
    uint32_t ksh_u = (uint32_t)__cvta_generic_to_shared(Ksh);
    uint32_t vt_u  = (uint32_t)__cvta_generic_to_shared(Vt);
    uint32_t kaddr = ksh_u + ((((sel >> 1)*8 + (lane & 7))*KSH_STR) + (sel & 1)*4) * 4;
    uint32_t vaddr = vt_u + (((sel >> 1)*8 + (lane & 7))*VT_STR) * 4 + (sel & 1)*16;

    float Of[2][4][4] = {};
    float lacc[2][2] = {};

    const uint32_t* tbp = g_tbt16 + h*NN*(NN/2);   // [j][k/2] half2

    __syncthreads();

    for (int kc = 0; kc < NN; kc += 32) {
        // ---- S = Q K^T ----
        float S[2][4][4] = {};
        #pragma unroll
        for (int ks = 0; ks < 2; ks++) {
            uint32_t b0[4], b1[4];
            ldsm_x4(b0[0], b1[0], b0[1], b1[1],
                    kaddr + ( kc      *KSH_STR + ks*8) * 4);
            ldsm_x4(b0[2], b1[2], b0[3], b1[3],
                    kaddr + ((kc + 16)*KSH_STR + ks*8) * 4);
            #pragma unroll
            for (int nt = 0; nt < 4; nt++) {
                mma_f16(S[0][nt], aq[0][ks], b0[nt], b1[nt]);
                mma_f16(S[1][nt], aq[1][ks], b0[nt], b1[nt]);
            }
        }
        // ---- biases + exp + row sums ----
        #pragma unroll
        for (int nt = 0; nt < 4; nt++) {
            int kcol = kc + nt*8 + t*2;
            int kw = kcol >> 1;
            float2 mbv = *(const float2*)&mb[kcol];
            #pragma unroll
            for (int mt = 0; mt < 2; mt++) {
                int row0 = q0 + mt*16 + g;
                float2 t0 = unpack_h2(tbp[ row0     *(NN/2) + kw]);
                float2 t1 = unpack_h2(tbp[(row0 + 8)*(NN/2) + kw]);
                float p0 = __expf(S[mt][nt][0] + mbv.x + t0.x);
                float p1 = __expf(S[mt][nt][1] + mbv.y + t0.y);
                float p2 = __expf(S[mt][nt][2] + mbv.x + t1.x);
                float p3 = __expf(S[mt][nt][3] + mbv.y + t1.y);
                S[mt][nt][0] = p0; S[mt][nt][1] = p1;
                S[mt][nt][2] = p2; S[mt][nt][3] = p3;
                lacc[mt][0] += p0 + p1;
                lacc[mt][1] += p2 + p3;
            }
        }
        // ---- O += P V ----
        #pragma unroll
        for (int kh = 0; kh < 2; kh++) {
            int kcp = (kc >> 1) + kh*8;
            uint32_t bv0[4], bv1[4];
            ldsm_x4(bv0[0], bv1[0], bv0[1], bv1[1], vaddr + kcp*4);
            ldsm_x4(bv0[2], bv1[2], bv0[3], bv1[3], vaddr + (16*VT_STR + kcp)*4);
            #pragma unroll
            for (int mt = 0; mt < 2; mt++) {
                uint32_t ap[4];
                ap[0] = pack_h2(S[mt][kh*2  ][0], S[mt][kh*2  ][1]);
                ap[1] = pack_h2(S[mt][kh*2  ][2], S[mt][kh*2  ][3]);
                ap[2] = pack_h2(S[mt][kh*2+1][0], S[mt][kh*2+1][1]);
                ap[3] = pack_h2(S[mt][kh*2+1][2], S[mt][kh*2+1][3]);
                #pragma unroll
                for (int ntd = 0; ntd < 4; ntd++)
                    mma_f16(Of[mt][ntd], ap, bv0[ntd], bv1[ntd]);
            }
        }
    }

    // ---- epilogue: normalize + gate + store ----
    uint32_t* obase = g_o32 + (size_t)(I*NN)*(HD/2) + h*16;
    const uint32_t* gbase = g_g32 + (size_t)(I*NN)*(HD/2) + h*16;
    #pragma unroll
    for (int mt = 0; mt < 2; mt++) {
        float l0 = lacc[mt][0];
        l0 += __shfl_xor_sync(0xffffffffu, l0, 1);
        l0 += __shfl_xor_sync(0xffffffffu, l0, 2);
        float l1 = lacc[mt][1];
        l1 += __shfl_xor_sync(0xffffffffu, l1, 1);
        l1 += __shfl_xor_sync(0xffffffffu, l1, 2);
        float inv0 = 1.0f / l0;
        float inv1 = 1.0f / l1;
        int row0 = q0 + mt*16 + g;
        int row1 = row0 + 8;
        #pragma unroll
        for (int ntd = 0; ntd < 4; ntd++) {
            int wp = ntd*4 + t;
            float2 bgv = *(const float2*)&bg[h*DD + 2*wp];
            float2 gg0 = unpack_h2(gbase[(size_t)row0*(HD/2) + wp]);
            float2 gg1 = unpack_h2(gbase[(size_t)row1*(HD/2) + wp]);
            float s00 = 1.0f / (1.0f + __expf(-(gg0.x + bgv.x)));
            float s01 = 1.0f / (1.0f + __expf(-(gg0.y + bgv.y)));
            float s10 = 1.0f / (1.0f + __expf(-(gg1.x + bgv.x)));
            float s11 = 1.0f / (1.0f + __expf(-(gg1.y + bgv.y)));
            obase[(size_t)row0*(HD/2) + wp] =
                pack_h2(Of[mt][ntd][0]*inv0*s00, Of[mt][ntd][1]*inv0*s01);
            obase[(size_t)row1*(HD/2) + wp] =
                pack_h2(Of[mt][ntd][2]*inv1*s10, Of[mt][ntd][3]*inv1*s11);
        }
    }
}

// ---------------------------------------------------------------
// Kernel 4: output projection (A = pre-gated o), f16 mma + scatter
// ---------------------------------------------------------------
__global__ __launch_bounds__(256, 2)
void gemm_out_f16(const float* __restrict__ bo, float* __restrict__ out)
{
    extern __shared__ uint32_t ts[];
    uint32_t* As = ts;
    uint32_t* Bs = ts + TS_SZ;

    int m0 = blockIdx.x * 128;

    int tid = threadIdx.x;
    int warp = tid >> 5, lane = tid & 31;
    int g = lane >> 2, t = lane & 3;
    int wm = warp >> 2, wn = warp & 3;
    int mbase = wm*64, nbase = wn*32;

    #pragma unroll
    for (int i = 0; i < 8; i++) {
        int f = tid + 256*i;
        int r = f >> 4, q4 = (f & 15) * 4;
        *(uint4*)&As[r*TS_STR + q4] = *(const uint4*)&g_o32[(size_t)(m0 + r)*(HD/2) + q4];
        *(uint4*)&Bs[r*TS_STR + q4] = *(const uint4*)&g_wop32[r*(HD/2) + q4];
    }
    __syncthreads();

    float acc[4][4][4] = {};

    #pragma unroll
    for (int ks = 0; ks < 8; ks++) {
        uint32_t af[4][4];
        #pragma unroll
        for (int mt = 0; mt < 4; mt++) {
            int r0 = mbase + mt*16 + g;
            af[mt][0] = As[ r0     *TS_STR + ks*8 + t    ];
            af[mt][1] = As[(r0 + 8)*TS_STR + ks*8 + t    ];
            af[mt][2] = As[ r0     *TS_STR + ks*8 + t + 4];
            af[mt][3] = As[(r0 + 8)*TS_STR + ks*8 + t + 4];
        }
        uint32_t bf0[4], bf1[4];
        #pragma unroll
        for (int nt = 0; nt < 4; nt++) {
            int nc = nbase + nt*8 + g;
            bf0[nt] = Bs[nc*TS_STR + ks*8 + t    ];
            bf1[nt] = Bs[nc*TS_STR + ks*8 + t + 4];
        }
        #pragma unroll
        for (int mt = 0; mt < 4; mt++)
            #pragma unroll
            for (int nt = 0; nt < 4; nt++)
                mma_f16(acc[mt][nt], af[mt], bf0[nt], bf1[nt]);
    }

    #pragma unroll
    for (int mt = 0; mt < 4; mt++) {
        int mr0 = m0 + mbase + mt*16 + g;
        int mr1 = mr0 + 8;
        int or0 = (mr0 & 255)*NN + (mr0 >> 8);   // swapaxes scatter
        int or1 = (mr1 & 255)*NN + (mr1 >> 8);
        #pragma unroll
        for (int nt = 0; nt < 4; nt++) {
            int col = nbase + nt*8 + 2*t;
            float2 b2 = *(const float2*)&bo[col];
            float2 w0 = make_float2(acc[mt][nt][0] + b2.x, acc[mt][nt][1] + b2.y);
            float2 w1 = make_float2(acc[mt][nt][2] + b2.x, acc[mt][nt][3] + b2.y);
            *(float2*)&out[or0*CC + col] = w0;
            *(float2*)&out[or1*CC + col] = w1;
        }
    }
}

// ---------------------------------------------------------------
extern "C" void kernel_launch(void* const* d_in, const int* in_sizes, int n_in,
                              void* d_out, int out_size)
{
    const float* x      = (const float*)d_in[0];
    const float* mask   = (const float*)d_in[1];
    const float* ln_w   = (const float*)d_in[2];
    const float* ln_b   = (const float*)d_in[3];
    const float* w_bias = (const float*)d_in[4];
    const float* wq     = (const float*)d_in[5];
    const float* wk     = (const float*)d_in[6];
    const float* wv     = (const float*)d_in[7];
    const float* wg     = (const float*)d_in[8];
    const float* bg     = (const float*)d_in[9];
    const float* wo     = (const float*)d_in[10];
    const float* bo     = (const float*)d_in[11];
    float* out = (float*)d_out;

    static bool attr_set = false;
    if (!attr_set) {
        cudaFuncSetAttribute(attn_f16, cudaFuncAttributeMaxDynamicSharedMemorySize,
                             ATTN_SMEM);
        cudaFuncSetAttribute(gemm_proj_f16, cudaFuncAttributeMaxDynamicSharedMemorySize,
                             GEMM_SMEM);
        cudaFuncSetAttribute(gemm_out_f16, cudaFuncAttributeMaxDynamicSharedMemorySize,
                             GEMM_SMEM);
        attr_set = true;
    }

    prep_weights<<<160, 256>>>(wq, wk, wv, wg, wo);
    ln_kernel<<<MM/8, 256>>>(x, ln_w, ln_b, w_bias);
    gemm_proj_f16<<<dim3(MM/128, 4), 256, GEMM_SMEM>>>();
    attn_f16<<<dim3(NN, HH), 256, ATTN_SMEM>>>(mask, bg);
    gemm_out_f16<<<dim3(MM/128, 1), 256, GEMM_SMEM>>>(bo, out);
}

// round 15
// speedup vs baseline: 1.1298x; 1.0262x over previous
#include <cuda_runtime.h>
#include <cuda_fp16.h>
#include <math.h>
#include <float.h>
#include <stdint.h>

#define NN 256
#define CC 128
#define HH 4
#define DD 32
#define MM (NN*NN)     // 65536
#define HD (HH*DD)     // 128
#define INF_ 1e9f
#define LN_EPS 1e-5f
#define LOG2E 1.4426950408889634f

// ---- scratch ----
__device__ uint32_t g_xn32[MM*CC/2];     // xn half2-packed along C
__device__ uint32_t g_q32 [MM*HD/2];     // q half, scale*log2e applied
__device__ uint32_t g_k32 [MM*HD/2];     // k half
__device__ uint32_t g_vt32[MM*HD/2];     // v half, layout [I][h][d][key]
__device__ uint32_t g_g32 [MM*HD/2];     // gate pre-sigmoid, half2
__device__ uint32_t g_o32 [MM*HD/2];     // attn out, normalized AND gated, half2
__device__ uint32_t g_tbt16[HH*NN*NN/2]; // [h][j][k/2] half2, *log2e
__device__ uint32_t g_wp32[4*HD*CC/2];   // [wi][n][kp]
__device__ uint32_t g_wop32[CC*HD/2];    // [n][kp]

// ---------------------------------------------------------------
__device__ __forceinline__ uint32_t pack_h2(float lo, float hi) {
    __half2 h = __floats2half2_rn(lo, hi);
    return *(uint32_t*)&h;
}
__device__ __forceinline__ float2 unpack_h2(uint32_t w) {
    __half2 h = *(__half2*)&w;
    return __half22float2(h);
}
__device__ __forceinline__ uint32_t hadd2_u(uint32_t a, uint32_t b) {
    __half2 r = __hadd2(*(__half2*)&a, *(__half2*)&b);
    return *(uint32_t*)&r;
}

__device__ __forceinline__ void mma_f16(float c[4], const uint32_t a[4],
                                        uint32_t b0, uint32_t b1) {
    asm volatile(
        "mma.sync.aligned.m16n8k16.row.col.f32.f16.f16.f32 "
        "{%0,%1,%2,%3}, {%4,%5,%6,%7}, {%8,%9}, {%0,%1,%2,%3};\n"
        : "+f"(c[0]), "+f"(c[1]), "+f"(c[2]), "+f"(c[3])
        : "r"(a[0]), "r"(a[1]), "r"(a[2]), "r"(a[3]), "r"(b0), "r"(b1));
}

__device__ __forceinline__ void ldsm_x4(uint32_t& r0, uint32_t& r1,
                                        uint32_t& r2, uint32_t& r3, uint32_t addr) {
    asm volatile("ldmatrix.sync.aligned.m8n8.x4.shared.b16 {%0,%1,%2,%3}, [%4];"
                 : "=r"(r0), "=r"(r1), "=r"(r2), "=r"(r3) : "r"(addr));
}

// ---------------------------------------------------------------
// Kernel 0: pack weights to half2
// ---------------------------------------------------------------
__global__ void prep_weights(const float* __restrict__ wq, const float* __restrict__ wk,
                             const float* __restrict__ wv, const float* __restrict__ wg,
                             const float* __restrict__ wo)
{
    int idx = blockIdx.x * 256 + threadIdx.x;
    if (idx < 4*HD*CC/2) {
        int wi = idx >> 13;
        int rem = idx & 8191;
        int n = rem >> 6, kp = rem & 63;
        const float* W = (wi == 0) ? wq : (wi == 1) ? wk : (wi == 2) ? wv : wg;
        g_wp32[idx] = pack_h2(W[(2*kp)*HD + n], W[(2*kp + 1)*HD + n]);
    } else {
        int r = idx - 4*HD*CC/2;
        int n = r >> 6, kp = r & 63;
        g_wop32[r] = pack_h2(wo[n*HD + 2*kp], wo[n*HD + 2*kp + 1]);
    }
}

// ---------------------------------------------------------------
// Kernel 1: LayerNorm (warp per row) + triangle-bias dots (*log2e)
// ---------------------------------------------------------------
__global__ __launch_bounds__(256)
void ln_kernel(const float* __restrict__ x,
               const float* __restrict__ ln_w,
               const float* __restrict__ ln_b,
               const float* __restrict__ w_bias)
{
    int warp = threadIdx.x >> 5, lane = threadIdx.x & 31;
    int m  = blockIdx.x * 8 + warp;
    int i1 = m >> 8;
    int i2 = m & 255;

    float4 v4 = *(const float4*)&x[(i2*NN + i1)*CC + lane*4];

    float s = v4.x + v4.y + v4.z + v4.w;
    #pragma unroll
    for (int o = 16; o > 0; o >>= 1) s += __shfl_xor_sync(0xffffffffu, s, o);
    float mu = s * (1.0f / CC);

    float dx = v4.x - mu, dy = v4.y - mu, dz = v4.z - mu, dw = v4.w - mu;
    float s2 = dx*dx + dy*dy + dz*dz + dw*dw;
    #pragma unroll
    for (int o = 16; o > 0; o >>= 1) s2 += __shfl_xor_sync(0xffffffffu, s2, o);
    float rs = rsqrtf(s2 * (1.0f / CC) + LN_EPS);

    float4 w4 = *(const float4*)&ln_w[lane*4];
    float4 b4 = *(const float4*)&ln_b[lane*4];
    float xn0 = dx*rs*w4.x + b4.x;
    float xn1 = dy*rs*w4.y + b4.y;
    float xn2 = dz*rs*w4.z + b4.z;
    float xn3 = dw*rs*w4.w + b4.w;

    *(uint2*)&g_xn32[m*(CC/2) + lane*2] =
        make_uint2(pack_h2(xn0, xn1), pack_h2(xn2, xn3));

    // triangle bias dots (*log2e); layout [h][j=i1][k=i2], half storage
    float acc[4];
    #pragma unroll
    for (int h = 0; h < 4; h++) {
        float4 wb = *(const float4*)&w_bias[h*CC + lane*4];
        acc[h] = xn0*wb.x + xn1*wb.y + xn2*wb.z + xn3*wb.w;
    }
    #pragma unroll
    for (int o = 16; o > 0; o >>= 1) {
        #pragma unroll
        for (int h = 0; h < 4; h++)
            acc[h] += __shfl_xor_sync(0xffffffffu, acc[h], o);
    }
    if (lane < 4)
        ((__half*)g_tbt16)[(lane*NN + i1)*NN + i2] = __float2half_rn(acc[lane] * LOG2E);
}

// ---------------------------------------------------------------
// Kernel 2: q/k/v/g projections, f16 mma, grid (512, 4)
// q scale includes LOG2E.
// ---------------------------------------------------------------
#define TS_STR 68
#define TS_SZ (128*TS_STR)
#define GEMM_SMEM (2*TS_SZ*4)     // 69632 B

__global__ __launch_bounds__(256, 2)
void gemm_proj_f16()
{
    extern __shared__ uint32_t ts[];
    uint32_t* As = ts;
    uint32_t* Bs = ts + TS_SZ;

    int wi = blockIdx.y;
    int m0 = blockIdx.x * 128;
    float osc = (wi == 0) ? 0.17677669529663689f * LOG2E : 1.0f;

    int tid = threadIdx.x;
    int warp = tid >> 5, lane = tid & 31;
    int g = lane >> 2, t = lane & 3;
    int wm = warp >> 2, wn = warp & 3;
    int mbase = wm*64, nbase = wn*32;

    const uint32_t* wp = g_wp32 + wi*HD*(CC/2);
    #pragma unroll
    for (int i = 0; i < 8; i++) {
        int f = tid + 256*i;
        int r = f >> 4, q4 = (f & 15) * 4;
        *(uint4*)&As[r*TS_STR + q4] = *(const uint4*)&g_xn32[(m0 + r)*(CC/2) + q4];
        *(uint4*)&Bs[r*TS_STR + q4] = *(const uint4*)&wp[r*(CC/2) + q4];
    }
    __syncthreads();

    float acc[4][4][4] = {};

    #pragma unroll
    for (int ks = 0; ks < 8; ks++) {
        uint32_t af[4][4];
        #pragma unroll
        for (int mt = 0; mt < 4; mt++) {
            int r0 = mbase + mt*16 + g;
            af[mt][0] = As[ r0     *TS_STR + ks*8 + t    ];
            af[mt][1] = As[(r0 + 8)*TS_STR + ks*8 + t    ];
            af[mt][2] = As[ r0     *TS_STR + ks*8 + t + 4];
            af[mt][3] = As[(r0 + 8)*TS_STR + ks*8 + t + 4];
        }
        uint32_t bf0[4], bf1[4];
        #pragma unroll
        for (int nt = 0; nt < 4; nt++) {
            int nc = nbase + nt*8 + g;
            bf0[nt] = Bs[nc*TS_STR + ks*8 + t    ];
            bf1[nt] = Bs[nc*TS_STR + ks*8 + t + 4];
        }
        #pragma unroll
        for (int mt = 0; mt < 4; mt++)
            #pragma unroll
            for (int nt = 0; nt < 4; nt++)
                mma_f16(acc[mt][nt], af[mt], bf0[nt], bf1[nt]);
    }

    #pragma unroll
    for (int mt = 0; mt < 4; mt++) {
        int row0 = m0 + mbase + mt*16 + g;
        int row1 = row0 + 8;
        #pragma unroll
        for (int nt = 0; nt < 4; nt++) {
            int ncol = nbase + nt*8 + 2*t;
            float c00 = acc[mt][nt][0]*osc, c01 = acc[mt][nt][1]*osc;
            float c10 = acc[mt][nt][2]*osc, c11 = acc[mt][nt][3]*osc;
            if (wi == 0) {
                g_q32[row0*(HD/2) + (ncol >> 1)] = pack_h2(c00, c01);
                g_q32[row1*(HD/2) + (ncol >> 1)] = pack_h2(c10, c11);
            } else if (wi == 1) {
                g_k32[row0*(HD/2) + (ncol >> 1)] = pack_h2(c00, c01);
                g_k32[row1*(HD/2) + (ncol >> 1)] = pack_h2(c10, c11);
            } else if (wi == 2) {
                __half* vt = (__half*)g_vt32;
                int h = ncol >> 5, d = ncol & 31;
                int I0 = row0 >> 8, key0 = row0 & 255;
                int I1 = row1 >> 8, key1 = row1 & 255;
                vt[((I0*HH + h)*DD + d    )*NN + key0] = __float2half_rn(c00);
                vt[((I0*HH + h)*DD + d + 1)*NN + key0] = __float2half_rn(c01);
                vt[((I1*HH + h)*DD + d    )*NN + key1] = __float2half_rn(c10);
                vt[((I1*HH + h)*DD + d + 1)*NN + key1] = __float2half_rn(c11);
            } else {
                g_g32[row0*(HD/2) + (ncol >> 1)] = pack_h2(c00, c01);
                g_g32[row1*(HD/2) + (ncol >> 1)] = pack_h2(c10, c11);
            }
        }
    }
}

// ---------------------------------------------------------------
// Kernel 3: f16 mma flash attention. Staged combined bias (tb+mask,
// *log2e, half) consumed via ldmatrix in C-fragment layout; exp2f.
// ---------------------------------------------------------------
#define KSH_STR 20
#define VT_STR 132
#define CB_STR 20
#define ATTN_SMEM ((NN*KSH_STR + DD*VT_STR + NN*CB_STR + 128) * 4)  // 58368 B

__global__ __launch_bounds__(256, 2)
void attn_f16(const float* __restrict__ mask, const float* __restrict__ bg)
{
    extern __shared__ uint32_t sm32[];
    uint32_t* Ksh  = sm32;                                   // [256][20]
    uint32_t* Vt   = sm32 + NN*KSH_STR;                      // [32][132]
    uint32_t* cb   = sm32 + NN*KSH_STR + DD*VT_STR;          // [256][20] (16 used)
    uint32_t* mbh2 = cb + NN*CB_STR;                         // [128] half2

    int I = blockIdx.x, h = blockIdx.y;
    int tid  = threadIdx.x;
    int warp = tid >> 5, lane = tid & 31;
    int g = lane >> 2, t = lane & 3;

    #pragma unroll
    for (int i = 0; i < 16; i++) {
        int idx = tid + 256*i;
        int key = idx >> 4, w = idx & 15;
        Ksh[key*KSH_STR + w] = g_k32[(size_t)(I*NN + key)*(HD/2) + h*16 + w];
    }
    {
        const uint32_t* vsrc = g_vt32 + (size_t)(I*HH + h)*DD*(NN/2);
        #pragma unroll
        for (int i = 0; i < 16; i++) {
            int idx = tid + 256*i;
            int d = idx >> 7, w = idx & 127;
            Vt[d*VT_STR + w] = vsrc[d*(NN/2) + w];
        }
    }
    if (tid < 128) {
        float m0 = LOG2E * INF_ * (mask[(2*tid    )*NN + I] - 1.0f);
        float m1 = LOG2E * INF_ * (mask[(2*tid + 1)*NN + I] - 1.0f);
        mbh2[tid] = pack_h2(m0, m1);
    }

    int q0 = warp * 32;
    const uint32_t* qbase = g_q32 + (size_t)(I*NN)*(HD/2) + h*16;
    uint32_t aq[2][2][4];
    #pragma unroll
    for (int mt = 0; mt < 2; mt++)
        #pragma unroll
        for (int ks = 0; ks < 2; ks++) {
            int r0 = q0 + mt*16 + g;
            aq[mt][ks][0] = qbase[(size_t) r0     *(HD/2) + ks*8 + t    ];
            aq[mt][ks][1] = qbase[(size_t)(r0 + 8)*(HD/2) + ks*8 + t    ];
            aq[mt][ks][2] = qbase[(size_t) r0     *(HD/2) + ks*8 + t + 4];
            aq[mt][ks][3] = qbase[(size_t)(r0 + 8)*(HD/2) + ks*8 + t + 4];
        }

    int sel = lane >> 3;
    uint32_t ksh_u = (uint32_t)__cvta_generic_to_shared(Ksh);
    uint32_t vt_u  = (uint32_t)__cvta_generic_to_shared(Vt);
    uint32_t cb_u  = (uint32_t)__cvta_generic_to_shared(cb);
    uint32_t kaddr = ksh_u + ((((sel >> 1)*8 + (lane & 7))*KSH_STR) + (sel & 1)*4) * 4;
    uint32_t vaddr = vt_u + (((sel >> 1)*8 + (lane & 7))*VT_STR) * 4 + (sel & 1)*16;
    // bias ldmatrix: matrix = lane>>3: (mat&1) row-halves, (mat>>1) col word +4
    uint32_t baddr[2];
    #pragma unroll
    for (int mt = 0; mt < 2; mt++)
        baddr[mt] = cb_u + ((q0 + mt*16 + (sel & 1)*8 + (lane & 7))*CB_STR
                            + (sel >> 1)*4) * 4;

    int srow = tid >> 2;            // 0..63
    int sw   = (tid & 3) * 4;       // 0,4,8,12

    float Of[2][4][4] = {};
    float lacc[2][2] = {};

    const uint32_t* tbp = g_tbt16 + h*NN*(NN/2);   // [j][k/2] half2 (*log2e)

    __syncthreads();

    for (int kc = 0; kc < NN; kc += 32) {
        // ---- S = Q K^T ----
        float S[2][4][4] = {};
        #pragma unroll
        for (int ks = 0; ks < 2; ks++) {
            uint32_t b0[4], b1[4];
            ldsm_x4(b0[0], b1[0], b0[1], b1[1],
                    kaddr + ( kc      *KSH_STR + ks*8) * 4);
            ldsm_x4(b0[2], b1[2], b0[3], b1[3],
                    kaddr + ((kc + 16)*KSH_STR + ks*8) * 4);
            #pragma unroll
            for (int nt = 0; nt < 4; nt++) {
                mma_f16(S[0][nt], aq[0][ks], b0[nt], b1[nt]);
                mma_f16(S[1][nt], aq[1][ks], b0[nt], b1[nt]);
            }
        }
        // ---- stage combined bias tile (256 rows x 16 words) ----
        __syncthreads();     // prior chunk's cb reads done
        {
            const uint32_t* tsrc = tbp + (kc >> 1);
            uint32_t mw0 = mbh2[(kc >> 1) + sw    ];
            uint32_t mw1 = mbh2[(kc >> 1) + sw + 1];
            uint32_t mw2 = mbh2[(kc >> 1) + sw + 2];
            uint32_t mw3 = mbh2[(kc >> 1) + sw + 3];
            #pragma unroll
            for (int u = 0; u < 4; u++) {
                int r = srow + u*64;
                uint4 tw = *(const uint4*)&tsrc[(size_t)r*(NN/2) + sw];
                tw.x = hadd2_u(tw.x, mw0);
                tw.y = hadd2_u(tw.y, mw1);
                tw.z = hadd2_u(tw.z, mw2);
                tw.w = hadd2_u(tw.w, mw3);
                *(uint4*)&cb[r*CB_STR + sw] = tw;
            }
        }
        __syncthreads();     // cb ready
        // ---- bias (ldmatrix, C-layout) + exp2 + row sums ----
        #pragma unroll
        for (int mt = 0; mt < 2; mt++) {
            #pragma unroll
            for (int s = 0; s < 2; s++) {
                uint32_t c0, c1, c2, c3;
                ldsm_x4(c0, c1, c2, c3, baddr[mt] + s*32);
                int nt0 = 2*s, nt1 = 2*s + 1;
                float2 f;
                f = unpack_h2(c0);
                float p0 = exp2f(S[mt][nt0][0] + f.x);
                float p1 = exp2f(S[mt][nt0][1] + f.y);
                f = unpack_h2(c1);
                float p2 = exp2f(S[mt][nt0][2] + f.x);
                float p3 = exp2f(S[mt][nt0][3] + f.y);
                f = unpack_h2(c2);
                float p4 = exp2f(S[mt][nt1][0] + f.x);
                float p5 = exp2f(S[mt][nt1][1] + f.y);
                f = unpack_h2(c3);
                float p6 = exp2f(S[mt][nt1][2] + f.x);
                float p7 = exp2f(S[mt][nt1][3] + f.y);
                S[mt][nt0][0] = p0; S[mt][nt0][1] = p1;
                S[mt][nt0][2] = p2; S[mt][nt0][3] = p3;
                S[mt][nt1][0] = p4; S[mt][nt1][1] = p5;
                S[mt][nt1][2] = p6; S[mt][nt1][3] = p7;
                lacc[mt][0] += p0 + p1 + p4 + p5;
                lacc[mt][1] += p2 + p3 + p6 + p7;
            }
        }
        // ---- O += P V ----
        #pragma unroll
        for (int kh = 0; kh < 2; kh++) {
            int kcp = (kc >> 1) + kh*8;
            uint32_t bv0[4], bv1[4];
            ldsm_x4(bv0[0], bv1[0], bv0[1], bv1[1], vaddr + kcp*4);
            ldsm_x4(bv0[2], bv1[2], bv0[3], bv1[3], vaddr + (16*VT_STR + kcp)*4);
            #pragma unroll
            for (int mt = 0; mt < 2; mt++) {
                uint32_t ap[4];
                ap[0] = pack_h2(S[mt][kh*2  ][0], S[mt][kh*2  ][1]);
                ap[1] = pack_h2(S[mt][kh*2  ][2], S[mt][kh*2  ][3]);
                ap[2] = pack_h2(S[mt][kh*2+1][0], S[mt][kh*2+1][1]);
                ap[3] = pack_h2(S[mt][kh*2+1][2], S[mt][kh*2+1][3]);
                #pragma unroll
                for (int ntd = 0; ntd < 4; ntd++)
                    mma_f16(Of[mt][ntd], ap, bv0[ntd], bv1[ntd]);
            }
        }
    }

    // ---- epilogue: normalize + gate + store ----
    uint32_t* obase = g_o32 + (size_t)(I*NN)*(HD/2) + h*16;
    const uint32_t* gbase = g_g32 + (size_t)(I*NN)*(HD/2) + h*16;
    #pragma unroll
    for (int mt = 0; mt < 2; mt++) {
        float l0 = lacc[mt][0];
        l0 += __shfl_xor_sync(0xffffffffu, l0, 1);
        l0 += __shfl_xor_sync(0xffffffffu, l0, 2);
        float l1 = lacc[mt][1];
        l1 += __shfl_xor_sync(0xffffffffu, l1, 1);
        l1 += __shfl_xor_sync(0xffffffffu, l1, 2);
        float inv0 = 1.0f / l0;
        float inv1 = 1.0f / l1;
        int row0 = q0 + mt*16 + g;
        int row1 = row0 + 8;
        #pragma unroll
        for (int ntd = 0; ntd < 4; ntd++) {
            int wp = ntd*4 + t;
            float2 bgv = *(const float2*)&bg[h*DD + 2*wp];
            float2 gg0 = unpack_h2(gbase[(size_t)row0*(HD/2) + wp]);
            float2 gg1 = unpack_h2(gbase[(size_t)row1*(HD/2) + wp]);
            float s00 = 1.0f / (1.0f + __expf(-(gg0.x + bgv.x)));
            float s01 = 1.0f / (1.0f + __expf(-(gg0.y + bgv.y)));
            float s10 = 1.0f / (1.0f + __expf(-(gg1.x + bgv.x)));
            float s11 = 1.0f / (1.0f + __expf(-(gg1.y + bgv.y)));
            obase[(size_t)row0*(HD/2) + wp] =
                pack_h2(Of[mt][ntd][0]*inv0*s00, Of[mt][ntd][1]*inv0*s01);
            obase[(size_t)row1*(HD/2) + wp] =
                pack_h2(Of[mt][ntd][2]*inv1*s10, Of[mt][ntd][3]*inv1*s11);
        }
    }
}

// ---------------------------------------------------------------
// Kernel 4: output projection (A = pre-gated o), f16 mma + scatter
// ---------------------------------------------------------------
__global__ __launch_bounds__(256, 2)
void gemm_out_f16(const float* __restrict__ bo, float* __restrict__ out)
{
    extern __shared__ uint32_t ts[];
    uint32_t* As = ts;
    uint32_t* Bs = ts + TS_SZ;

    int m0 = blockIdx.x * 128;

    int tid = threadIdx.x;
    int warp = tid >> 5, lane = tid & 31;
    int g = lane >> 2, t = lane & 3;
    int wm = warp >> 2, wn = warp & 3;
    int mbase = wm*64, nbase = wn*32;

    #pragma unroll
    for (int i = 0; i < 8; i++) {
        int f = tid + 256*i;
        int r = f >> 4, q4 = (f & 15) * 4;
        *(uint4*)&As[r*TS_STR + q4] = *(const uint4*)&g_o32[(size_t)(m0 + r)*(HD/2) + q4];
        *(uint4*)&Bs[r*TS_STR + q4] = *(const uint4*)&g_wop32[r*(HD/2) + q4];
    }
    __syncthreads();

    float acc[4][4][4] = {};

    #pragma unroll
    for (int ks = 0; ks < 8; ks++) {
        uint32_t af[4][4];
        #pragma unroll
        for (int mt = 0; mt < 4; mt++) {
            int r0 = mbase + mt*16 + g;
            af[mt][0] = As[ r0     *TS_STR + ks*8 + t    ];
            af[mt][1] = As[(r0 + 8)*TS_STR + ks*8 + t    ];
            af[mt][2] = As[ r0     *TS_STR + ks*8 + t + 4];
            af[mt][3] = As[(r0 + 8)*TS_STR + ks*8 + t + 4];
        }
        uint32_t bf0[4], bf1[4];
        #pragma unroll
        for (int nt = 0; nt < 4; nt++) {
            int nc = nbase + nt*8 + g;
            bf0[nt] = Bs[nc*TS_STR + ks*8 + t    ];
            bf1[nt] = Bs[nc*TS_STR + ks*8 + t + 4];
        }
        #pragma unroll
        for (int mt = 0; mt < 4; mt++)
            #pragma unroll
            for (int nt = 0; nt < 4; nt++)
                mma_f16(acc[mt][nt], af[mt], bf0[nt], bf1[nt]);
    }

    #pragma unroll
    for (int mt = 0; mt < 4; mt++) {
        int mr0 = m0 + mbase + mt*16 + g;
        int mr1 = mr0 + 8;
        int or0 = (mr0 & 255)*NN + (mr0 >> 8);   // swapaxes scatter
        int or1 = (mr1 & 255)*NN + (mr1 >> 8);
        #pragma unroll
        for (int nt = 0; nt < 4; nt++) {
            int col = nbase + nt*8 + 2*t;
            float2 b2 = *(const float2*)&bo[col];
            float2 w0 = make_float2(acc[mt][nt][0] + b2.x, acc[mt][nt][1] + b2.y);
            float2 w1 = make_float2(acc[mt][nt][2] + b2.x, acc[mt][nt][3] + b2.y);
            *(float2*)&out[or0*CC + col] = w0;
            *(float2*)&out[or1*CC + col] = w1;
        }
    }
}

// ---------------------------------------------------------------
extern "C" void kernel_launch(void* const* d_in, const int* in_sizes, int n_in,
                              void* d_out, int out_size)
{
    const float* x      = (const float*)d_in[0];
    const float* mask   = (const float*)d_in[1];
    const float* ln_w   = (const float*)d_in[2];
    const float* ln_b   = (const float*)d_in[3];
    const float* w_bias = (const float*)d_in[4];
    const float* wq     = (const float*)d_in[5];
    const float* wk     = (const float*)d_in[6];
    const float* wv     = (const float*)d_in[7];
    const float* wg     = (const float*)d_in[8];
    const float* bg     = (const float*)d_in[9];
    const float* wo     = (const float*)d_in[10];
    const float* bo     = (const float*)d_in[11];
    float* out = (float*)d_out;

    static bool attr_set = false;
    if (!attr_set) {
        cudaFuncSetAttribute(attn_f16, cudaFuncAttributeMaxDynamicSharedMemorySize,
                             ATTN_SMEM);
        cudaFuncSetAttribute(gemm_proj_f16, cudaFuncAttributeMaxDynamicSharedMemorySize,
                             GEMM_SMEM);
        cudaFuncSetAttribute(gemm_out_f16, cudaFuncAttributeMaxDynamicSharedMemorySize,
                             GEMM_SMEM);
        attr_set = true;
    }

    prep_weights<<<160, 256>>>(wq, wk, wv, wg, wo);
    ln_kernel<<<MM/8, 256>>>(x, ln_w, ln_b, w_bias);
    gemm_proj_f16<<<dim3(MM/128, 4), 256, GEMM_SMEM>>>();
    attn_f16<<<dim3(NN, HH), 256, ATTN_SMEM>>>(mask, bg);
    gemm_out_f16<<<dim3(MM/128, 1), 256, GEMM_SMEM>>>(bo, out);
}

// round 16
// speedup vs baseline: 1.1484x; 1.0165x over previous
#include <cuda_runtime.h>
#include <cuda_fp16.h>
#include <math.h>
#include <float.h>
#include <stdint.h>

#define NN 256
#define CC 128
#define HH 4
#define DD 32
#define MM (NN*NN)     // 65536
#define HD (HH*DD)     // 128
#define INF_ 1e9f
#define LN_EPS 1e-5f
#define LOG2E 1.4426950408889634f

// ---- scratch ----
__device__ uint32_t g_xn32[MM*CC/2];     // xn half2-packed along C
__device__ uint32_t g_q32 [MM*HD/2];     // q half, scale*log2e applied
__device__ uint32_t g_k32 [MM*HD/2];     // k half
__device__ uint32_t g_vt32[MM*HD/2];     // v half, layout [I][h][d][key]
__device__ uint32_t g_g32 [MM*HD/2];     // gate pre-sigmoid, half2
__device__ uint32_t g_o32 [MM*HD/2];     // attn out, normalized AND gated, half2
__device__ uint32_t g_tbt16[HH*NN*NN/2]; // [h][j][k/2] half2, *log2e
__device__ uint32_t g_wp32[4*HD*CC/2];   // [wi][n][kp]
__device__ uint32_t g_wop32[CC*HD/2];    // [n][kp]

// ---------------------------------------------------------------
__device__ __forceinline__ uint32_t pack_h2(float lo, float hi) {
    __half2 h = __floats2half2_rn(lo, hi);
    return *(uint32_t*)&h;
}
__device__ __forceinline__ float2 unpack_h2(uint32_t w) {
    __half2 h = *(__half2*)&w;
    return __half22float2(h);
}
__device__ __forceinline__ uint32_t hadd2_u(uint32_t a, uint32_t b) {
    __half2 r = __hadd2(*(__half2*)&a, *(__half2*)&b);
    return *(uint32_t*)&r;
}
__device__ __forceinline__ float ex2(float x) {
    float r;
    asm("ex2.approx.ftz.f32 %0, %1;" : "=f"(r) : "f"(x));
    return r;
}

__device__ __forceinline__ void mma_f16(float c[4], const uint32_t a[4],
                                        uint32_t b0, uint32_t b1) {
    asm volatile(
        "mma.sync.aligned.m16n8k16.row.col.f32.f16.f16.f32 "
        "{%0,%1,%2,%3}, {%4,%5,%6,%7}, {%8,%9}, {%0,%1,%2,%3};\n"
        : "+f"(c[0]), "+f"(c[1]), "+f"(c[2]), "+f"(c[3])
        : "r"(a[0]), "r"(a[1]), "r"(a[2]), "r"(a[3]), "r"(b0), "r"(b1));
}

__device__ __forceinline__ void ldsm_x4(uint32_t& r0, uint32_t& r1,
                                        uint32_t& r2, uint32_t& r3, uint32_t addr) {
    asm volatile("ldmatrix.sync.aligned.m8n8.x4.shared.b16 {%0,%1,%2,%3}, [%4];"
                 : "=r"(r0), "=r"(r1), "=r"(r2), "=r"(r3) : "r"(addr));
}

// ---------------------------------------------------------------
// Kernel 0: pack weights to half2
// ---------------------------------------------------------------
__global__ void prep_weights(const float* __restrict__ wq, const float* __restrict__ wk,
                             const float* __restrict__ wv, const float* __restrict__ wg,
                             const float* __restrict__ wo)
{
    int idx = blockIdx.x * 256 + threadIdx.x;
    if (idx < 4*HD*CC/2) {
        int wi = idx >> 13;
        int rem = idx & 8191;
        int n = rem >> 6, kp = rem & 63;
        const float* W = (wi == 0) ? wq : (wi == 1) ? wk : (wi == 2) ? wv : wg;
        g_wp32[idx] = pack_h2(W[(2*kp)*HD + n], W[(2*kp + 1)*HD + n]);
    } else {
        int r = idx - 4*HD*CC/2;
        int n = r >> 6, kp = r & 63;
        g_wop32[r] = pack_h2(wo[n*HD + 2*kp], wo[n*HD + 2*kp + 1]);
    }
}

// ---------------------------------------------------------------
// Kernel 1: LayerNorm (warp per row) + triangle-bias dots (*log2e)
// ---------------------------------------------------------------
__global__ __launch_bounds__(256)
void ln_kernel(const float* __restrict__ x,
               const float* __restrict__ ln_w,
               const float* __restrict__ ln_b,
               const float* __restrict__ w_bias)
{
    int warp = threadIdx.x >> 5, lane = threadIdx.x & 31;
    int m  = blockIdx.x * 8 + warp;
    int i1 = m >> 8;
    int i2 = m & 255;

    float4 v4 = *(const float4*)&x[(i2*NN + i1)*CC + lane*4];

    float s = v4.x + v4.y + v4.z + v4.w;
    #pragma unroll
    for (int o = 16; o > 0; o >>= 1) s += __shfl_xor_sync(0xffffffffu, s, o);
    float mu = s * (1.0f / CC);

    float dx = v4.x - mu, dy = v4.y - mu, dz = v4.z - mu, dw = v4.w - mu;
    float s2 = dx*dx + dy*dy + dz*dz + dw*dw;
    #pragma unroll
    for (int o = 16; o > 0; o >>= 1) s2 += __shfl_xor_sync(0xffffffffu, s2, o);
    float rs = rsqrtf(s2 * (1.0f / CC) + LN_EPS);

    float4 w4 = *(const float4*)&ln_w[lane*4];
    float4 b4 = *(const float4*)&ln_b[lane*4];
    float xn0 = dx*rs*w4.x + b4.x;
    float xn1 = dy*rs*w4.y + b4.y;
    float xn2 = dz*rs*w4.z + b4.z;
    float xn3 = dw*rs*w4.w + b4.w;

    *(uint2*)&g_xn32[m*(CC/2) + lane*2] =
        make_uint2(pack_h2(xn0, xn1), pack_h2(xn2, xn3));

    // triangle bias dots (*log2e); layout [h][j=i1][k=i2], half storage
    float acc[4];
    #pragma unroll
    for (int h = 0; h < 4; h++) {
        float4 wb = *(const float4*)&w_bias[h*CC + lane*4];
        acc[h] = xn0*wb.x + xn1*wb.y + xn2*wb.z + xn3*wb.w;
    }
    #pragma unroll
    for (int o = 16; o > 0; o >>= 1) {
        #pragma unroll
        for (int h = 0; h < 4; h++)
            acc[h] += __shfl_xor_sync(0xffffffffu, acc[h], o);
    }
    if (lane < 4)
        ((__half*)g_tbt16)[(lane*NN + i1)*NN + i2] = __float2half_rn(acc[lane] * LOG2E);
}

// ---------------------------------------------------------------
// Kernel 2: q/k/v/g projections, f16 mma, grid (512, 4)
// ---------------------------------------------------------------
#define TS_STR 68
#define TS_SZ (128*TS_STR)
#define GEMM_SMEM (2*TS_SZ*4)     // 69632 B

__global__ __launch_bounds__(256, 2)
void gemm_proj_f16()
{
    extern __shared__ uint32_t ts[];
    uint32_t* As = ts;
    uint32_t* Bs = ts + TS_SZ;

    int wi = blockIdx.y;
    int m0 = blockIdx.x * 128;
    float osc = (wi == 0) ? 0.17677669529663689f * LOG2E : 1.0f;

    int tid = threadIdx.x;
    int warp = tid >> 5, lane = tid & 31;
    int g = lane >> 2, t = lane & 3;
    int wm = warp >> 2, wn = warp & 3;
    int mbase = wm*64, nbase = wn*32;

    const uint32_t* wp = g_wp32 + wi*HD*(CC/2);
    #pragma unroll
    for (int i = 0; i < 8; i++) {
        int f = tid + 256*i;
        int r = f >> 4, q4 = (f & 15) * 4;
        *(uint4*)&As[r*TS_STR + q4] = *(const uint4*)&g_xn32[(m0 + r)*(CC/2) + q4];
        *(uint4*)&Bs[r*TS_STR + q4] = *(const uint4*)&wp[r*(CC/2) + q4];
    }
    __syncthreads();

    float acc[4][4][4] = {};

    #pragma unroll
    for (int ks = 0; ks < 8; ks++) {
        uint32_t af[4][4];
        #pragma unroll
        for (int mt = 0; mt < 4; mt++) {
            int r0 = mbase + mt*16 + g;
            af[mt][0] = As[ r0     *TS_STR + ks*8 + t    ];
            af[mt][1] = As[(r0 + 8)*TS_STR + ks*8 + t    ];
            af[mt][2] = As[ r0     *TS_STR + ks*8 + t + 4];
            af[mt][3] = As[(r0 + 8)*TS_STR + ks*8 + t + 4];
        }
        uint32_t bf0[4], bf1[4];
        #pragma unroll
        for (int nt = 0; nt < 4; nt++) {
            int nc = nbase + nt*8 + g;
            bf0[nt] = Bs[nc*TS_STR + ks*8 + t    ];
            bf1[nt] = Bs[nc*TS_STR + ks*8 + t + 4];
        }
        #pragma unroll
        for (int mt = 0; mt < 4; mt++)
            #pragma unroll
            for (int nt = 0; nt < 4; nt++)
                mma_f16(acc[mt][nt], af[mt], bf0[nt], bf1[nt]);
    }

    #pragma unroll
    for (int mt = 0; mt < 4; mt++) {
        int row0 = m0 + mbase + mt*16 + g;
        int row1 = row0 + 8;
        #pragma unroll
        for (int nt = 0; nt < 4; nt++) {
            int ncol = nbase + nt*8 + 2*t;
            float c00 = acc[mt][nt][0]*osc, c01 = acc[mt][nt][1]*osc;
            float c10 = acc[mt][nt][2]*osc, c11 = acc[mt][nt][3]*osc;
            if (wi == 0) {
                g_q32[row0*(HD/2) + (ncol >> 1)] = pack_h2(c00, c01);
                g_q32[row1*(HD/2) + (ncol >> 1)] = pack_h2(c10, c11);
            } else if (wi == 1) {
                g_k32[row0*(HD/2) + (ncol >> 1)] = pack_h2(c00, c01);
                g_k32[row1*(HD/2) + (ncol >> 1)] = pack_h2(c10, c11);
            } else if (wi == 2) {
                __half* vt = (__half*)g_vt32;
                int h = ncol >> 5, d = ncol & 31;
                int I0 = row0 >> 8, key0 = row0 & 255;
                int I1 = row1 >> 8, key1 = row1 & 255;
                vt[((I0*HH + h)*DD + d    )*NN + key0] = __float2half_rn(c00);
                vt[((I0*HH + h)*DD + d + 1)*NN + key0] = __float2half_rn(c01);
                vt[((I1*HH + h)*DD + d    )*NN + key1] = __float2half_rn(c10);
                vt[((I1*HH + h)*DD + d + 1)*NN + key1] = __float2half_rn(c11);
            } else {
                g_g32[row0*(HD/2) + (ncol >> 1)] = pack_h2(c00, c01);
                g_g32[row1*(HD/2) + (ncol >> 1)] = pack_h2(c10, c11);
            }
        }
    }
}

// ---------------------------------------------------------------
// Kernel 3: f16 mma flash attention. Triple-buffered combined-bias
// staging (1 sync/chunk), ldmatrix C-layout bias, MUFU ex2.
// ---------------------------------------------------------------
#define KSH_STR 20
#define VT_STR 132
#define CB_STR 20
#define NBUF 3
#define ATTN_SMEM ((NN*KSH_STR + DD*VT_STR + NBUF*NN*CB_STR + 128) * 4)  // 99328 B

__global__ __launch_bounds__(256, 2)
void attn_f16(const float* __restrict__ mask, const float* __restrict__ bg)
{
    extern __shared__ uint32_t sm32[];
    uint32_t* Ksh  = sm32;                                   // [256][20]
    uint32_t* Vt   = sm32 + NN*KSH_STR;                      // [32][132]
    uint32_t* cb   = sm32 + NN*KSH_STR + DD*VT_STR;          // [3][256][20]
    uint32_t* mbh2 = cb + NBUF*NN*CB_STR;                    // [128] half2

    int I = blockIdx.x, h = blockIdx.y;
    int tid  = threadIdx.x;
    int warp = tid >> 5, lane = tid & 31;
    int g = lane >> 2, t = lane & 3;

    #pragma unroll
    for (int i = 0; i < 16; i++) {
        int idx = tid + 256*i;
        int key = idx >> 4, w = idx & 15;
        Ksh[key*KSH_STR + w] = g_k32[(size_t)(I*NN + key)*(HD/2) + h*16 + w];
    }
    {
        const uint32_t* vsrc = g_vt32 + (size_t)(I*HH + h)*DD*(NN/2);
        #pragma unroll
        for (int i = 0; i < 16; i++) {
            int idx = tid + 256*i;
            int d = idx >> 7, w = idx & 127;
            Vt[d*VT_STR + w] = vsrc[d*(NN/2) + w];
        }
    }
    if (tid < 128) {
        float m0 = LOG2E * INF_ * (mask[(2*tid    )*NN + I] - 1.0f);
        float m1 = LOG2E * INF_ * (mask[(2*tid + 1)*NN + I] - 1.0f);
        mbh2[tid] = pack_h2(m0, m1);
    }

    int q0 = warp * 32;
    const uint32_t* qbase = g_q32 + (size_t)(I*NN)*(HD/2) + h*16;
    uint32_t aq[2][2][4];
    #pragma unroll
    for (int mt = 0; mt < 2; mt++)
        #pragma unroll
        for (int ks = 0; ks < 2; ks++) {
            int r0 = q0 + mt*16 + g;
            aq[mt][ks][0] = qbase[(size_t) r0     *(HD/2) + ks*8 + t    ];
            aq[mt][ks][1] = qbase[(size_t)(r0 + 8)*(HD/2) + ks*8 + t    ];
            aq[mt][ks][2] = qbase[(size_t) r0     *(HD/2) + ks*8 + t + 4];
            aq[mt][ks][3] = qbase[(size_t)(r0 + 8)*(HD/2) + ks*8 + t + 4];
        }

    int sel = lane >> 3;
    uint32_t ksh_u = (uint32_t)__cvta_generic_to_shared(Ksh);
    uint32_t vt_u  = (uint32_t)__cvta_generic_to_shared(Vt);
    uint32_t cb_u  = (uint32_t)__cvta_generic_to_shared(cb);
    uint32_t kaddr = ksh_u + ((((sel >> 1)*8 + (lane & 7))*KSH_STR) + (sel & 1)*4) * 4;
    uint32_t vaddr = vt_u + (((sel >> 1)*8 + (lane & 7))*VT_STR) * 4 + (sel & 1)*16;
    uint32_t baddr[2];
    #pragma unroll
    for (int mt = 0; mt < 2; mt++)
        baddr[mt] = cb_u + ((q0 + mt*16 + (sel & 1)*8 + (lane & 7))*CB_STR
                            + (sel >> 1)*4) * 4;

    int srow = tid >> 2;            // 0..63
    int sw   = (tid & 3) * 4;       // 0,4,8,12

    const uint32_t* tbp = g_tbt16 + h*NN*(NN/2);   // [j][k/2] half2 (*log2e)

    // stager: combined bias for chunk ci into slot ci%NBUF
    auto stage_cb = [&](int ci) {
        uint32_t* dst = cb + (ci % NBUF)*NN*CB_STR;
        const uint32_t* tsrc = tbp + ci*16;
        uint32_t mw0 = mbh2[ci*16 + sw    ];
        uint32_t mw1 = mbh2[ci*16 + sw + 1];
        uint32_t mw2 = mbh2[ci*16 + sw + 2];
        uint32_t mw3 = mbh2[ci*16 + sw + 3];
        #pragma unroll
        for (int u = 0; u < 4; u++) {
            int r = srow + u*64;
            uint4 tw = *(const uint4*)&tsrc[(size_t)r*(NN/2) + sw];
            tw.x = hadd2_u(tw.x, mw0);
            tw.y = hadd2_u(tw.y, mw1);
            tw.z = hadd2_u(tw.z, mw2);
            tw.w = hadd2_u(tw.w, mw3);
            *(uint4*)&dst[r*CB_STR + sw] = tw;
        }
    };

    float Of[2][4][4] = {};
    float lacc[2][2] = {};

    __syncthreads();        // mbh2 visible before stage_cb(0) reads it
    stage_cb(0);
    __syncthreads();        // K/V + cb slot0 ready

    for (int ci = 0; ci < 8; ci++) {
        int kc = ci*32;
        // ---- stage next chunk's bias (overlaps with S mma latency) ----
        if (ci < 7) stage_cb(ci + 1);
        // ---- S = Q K^T ----
        float S[2][4][4] = {};
        #pragma unroll
        for (int ks = 0; ks < 2; ks++) {
            uint32_t b0[4], b1[4];
            ldsm_x4(b0[0], b1[0], b0[1], b1[1],
                    kaddr + ( kc      *KSH_STR + ks*8) * 4);
            ldsm_x4(b0[2], b1[2], b0[3], b1[3],
                    kaddr + ((kc + 16)*KSH_STR + ks*8) * 4);
            #pragma unroll
            for (int nt = 0; nt < 4; nt++) {
                mma_f16(S[0][nt], aq[0][ks], b0[nt], b1[nt]);
                mma_f16(S[1][nt], aq[1][ks], b0[nt], b1[nt]);
            }
        }
        // ---- bias (ldmatrix from current slot) + ex2 + row sums ----
        uint32_t slotoff = (ci % NBUF)*NN*CB_STR*4;
        #pragma unroll
        for (int mt = 0; mt < 2; mt++) {
            #pragma unroll
            for (int s = 0; s < 2; s++) {
                uint32_t c0, c1, c2, c3;
                ldsm_x4(c0, c1, c2, c3, baddr[mt] + slotoff + s*32);
                int nt0 = 2*s, nt1 = 2*s + 1;
                float2 f;
                f = unpack_h2(c0);
                float p0 = ex2(S[mt][nt0][0] + f.x);
                float p1 = ex2(S[mt][nt0][1] + f.y);
                f = unpack_h2(c1);
                float p2 = ex2(S[mt][nt0][2] + f.x);
                float p3 = ex2(S[mt][nt0][3] + f.y);
                f = unpack_h2(c2);
                float p4 = ex2(S[mt][nt1][0] + f.x);
                float p5 = ex2(S[mt][nt1][1] + f.y);
                f = unpack_h2(c3);
                float p6 = ex2(S[mt][nt1][2] + f.x);
                float p7 = ex2(S[mt][nt1][3] + f.y);
                S[mt][nt0][0] = p0; S[mt][nt0][1] = p1;
                S[mt][nt0][2] = p2; S[mt][nt0][3] = p3;
                S[mt][nt1][0] = p4; S[mt][nt1][1] = p5;
                S[mt][nt1][2] = p6; S[mt][nt1][3] = p7;
                lacc[mt][0] += p0 + p1 + p4 + p5;
                lacc[mt][1] += p2 + p3 + p6 + p7;
            }
        }
        // ---- O += P V ----
        #pragma unroll
        for (int kh = 0; kh < 2; kh++) {
            int kcp = (kc >> 1) + kh*8;
            uint32_t bv0[4], bv1[4];
            ldsm_x4(bv0[0], bv1[0], bv0[1], bv1[1], vaddr + kcp*4);
            ldsm_x4(bv0[2], bv1[2], bv0[3], bv1[3], vaddr + (16*VT_STR + kcp)*4);
            #pragma unroll
            for (int mt = 0; mt < 2; mt++) {
                uint32_t ap[4];
                ap[0] = pack_h2(S[mt][kh*2  ][0], S[mt][kh*2  ][1]);
                ap[1] = pack_h2(S[mt][kh*2  ][2], S[mt][kh*2  ][3]);
                ap[2] = pack_h2(S[mt][kh*2+1][0], S[mt][kh*2+1][1]);
                ap[3] = pack_h2(S[mt][kh*2+1][2], S[mt][kh*2+1][3]);
                #pragma unroll
                for (int ntd = 0; ntd < 4; ntd++)
                    mma_f16(Of[mt][ntd], ap, bv0[ntd], bv1[ntd]);
            }
        }
        __syncthreads();    // separates cb reads (this iter) from writes 2 iters out
    }

    // ---- epilogue: normalize + gate + store ----
    uint32_t* obase = g_o32 + (size_t)(I*NN)*(HD/2) + h*16;
    const uint32_t* gbase = g_g32 + (size_t)(I*NN)*(HD/2) + h*16;
    #pragma unroll
    for (int mt = 0; mt < 2; mt++) {
        float l0 = lacc[mt][0];
        l0 += __shfl_xor_sync(0xffffffffu, l0, 1);
        l0 += __shfl_xor_sync(0xffffffffu, l0, 2);
        float l1 = lacc[mt][1];
        l1 += __shfl_xor_sync(0xffffffffu, l1, 1);
        l1 += __shfl_xor_sync(0xffffffffu, l1, 2);
        float inv0 = 1.0f / l0;
        float inv1 = 1.0f / l1;
        int row0 = q0 + mt*16 + g;
        int row1 = row0 + 8;
        #pragma unroll
        for (int ntd = 0; ntd < 4; ntd++) {
            int wp = ntd*4 + t;
            float2 bgv = *(const float2*)&bg[h*DD + 2*wp];
            float2 gg0 = unpack_h2(gbase[(size_t)row0*(HD/2) + wp]);
            float2 gg1 = unpack_h2(gbase[(size_t)row1*(HD/2) + wp]);
            float s00 = 1.0f / (1.0f + __expf(-(gg0.x + bgv.x)));
            float s01 = 1.0f / (1.0f + __expf(-(gg0.y + bgv.y)));
            float s10 = 1.0f / (1.0f + __expf(-(gg1.x + bgv.x)));
            float s11 = 1.0f / (1.0f + __expf(-(gg1.y + bgv.y)));
            obase[(size_t)row0*(HD/2) + wp] =
                pack_h2(Of[mt][ntd][0]*inv0*s00, Of[mt][ntd][1]*inv0*s01);
            obase[(size_t)row1*(HD/2) + wp] =
                pack_h2(Of[mt][ntd][2]*inv1*s10, Of[mt][ntd][3]*inv1*s11);
        }
    }
}

// ---------------------------------------------------------------
// Kernel 4: output projection (A = pre-gated o), f16 mma + scatter
// ---------------------------------------------------------------
__global__ __launch_bounds__(256, 2)
void gemm_out_f16(const float* __restrict__ bo, float* __restrict__ out)
{
    extern __shared__ uint32_t ts[];
    uint32_t* As = ts;
    uint32_t* Bs = ts + TS_SZ;

    int m0 = blockIdx.x * 128;

    int tid = threadIdx.x;
    int warp = tid >> 5, lane = tid & 31;
    int g = lane >> 2, t = lane & 3;
    int wm = warp >> 2, wn = warp & 3;
    int mbase = wm*64, nbase = wn*32;

    #pragma unroll
    for (int i = 0; i < 8; i++) {
        int f = tid + 256*i;
        int r = f >> 4, q4 = (f & 15) * 4;
        *(uint4*)&As[r*TS_STR + q4] = *(const uint4*)&g_o32[(size_t)(m0 + r)*(HD/2) + q4];
        *(uint4*)&Bs[r*TS_STR + q4] = *(const uint4*)&g_wop32[r*(HD/2) + q4];
    }
    __syncthreads();

    float acc[4][4][4] = {};

    #pragma unroll
    for (int ks = 0; ks < 8; ks++) {
        uint32_t af[4][4];
        #pragma unroll
        for (int mt = 0; mt < 4; mt++) {
            int r0 = mbase + mt*16 + g;
            af[mt][0] = As[ r0     *TS_STR + ks*8 + t    ];
            af[mt][1] = As[(r0 + 8)*TS_STR + ks*8 + t    ];
            af[mt][2] = As[ r0     *TS_STR + ks*8 + t + 4];
            af[mt][3] = As[(r0 + 8)*TS_STR + ks*8 + t + 4];
        }
        uint32_t bf0[4], bf1[4];
        #pragma unroll
        for (int nt = 0; nt < 4; nt++) {
            int nc = nbase + nt*8 + g;
            bf0[nt] = Bs[nc*TS_STR + ks*8 + t    ];
            bf1[nt] = Bs[nc*TS_STR + ks*8 + t + 4];
        }
        #pragma unroll
        for (int mt = 0; mt < 4; mt++)
            #pragma unroll
            for (int nt = 0; nt < 4; nt++)
                mma_f16(acc[mt][nt], af[mt], bf0[nt], bf1[nt]);
    }

    #pragma unroll
    for (int mt = 0; mt < 4; mt++) {
        int mr0 = m0 + mbase + mt*16 + g;
        int mr1 = mr0 + 8;
        int or0 = (mr0 & 255)*NN + (mr0 >> 8);   // swapaxes scatter
        int or1 = (mr1 & 255)*NN + (mr1 >> 8);
        #pragma unroll
        for (int nt = 0; nt < 4; nt++) {
            int col = nbase + nt*8 + 2*t;
            float2 b2 = *(const float2*)&bo[col];
            float2 w0 = make_float2(acc[mt][nt][0] + b2.x, acc[mt][nt][1] + b2.y);
            float2 w1 = make_float2(acc[mt][nt][2] + b2.x, acc[mt][nt][3] + b2.y);
            *(float2*)&out[or0*CC + col] = w0;
            *(float2*)&out[or1*CC + col] = w1;
        }
    }
}

// ---------------------------------------------------------------
extern "C" void kernel_launch(void* const* d_in, const int* in_sizes, int n_in,
                              void* d_out, int out_size)
{
    const float* x      = (const float*)d_in[0];
    const float* mask   = (const float*)d_in[1];
    const float* ln_w   = (const float*)d_in[2];
    const float* ln_b   = (const float*)d_in[3];
    const float* w_bias = (const float*)d_in[4];
    const float* wq     = (const float*)d_in[5];
    const float* wk     = (const float*)d_in[6];
    const float* wv     = (const float*)d_in[7];
    const float* wg     = (const float*)d_in[8];
    const float* bg     = (const float*)d_in[9];
    const float* wo     = (const float*)d_in[10];
    const float* bo     = (const float*)d_in[11];
    float* out = (float*)d_out;

    static bool attr_set = false;
    if (!attr_set) {
        cudaFuncSetAttribute(attn_f16, cudaFuncAttributeMaxDynamicSharedMemorySize,
                             ATTN_SMEM);
        cudaFuncSetAttribute(gemm_proj_f16, cudaFuncAttributeMaxDynamicSharedMemorySize,
                             GEMM_SMEM);
        cudaFuncSetAttribute(gemm_out_f16, cudaFuncAttributeMaxDynamicSharedMemorySize,
                             GEMM_SMEM);
        attr_set = true;
    }

    prep_weights<<<160, 256>>>(wq, wk, wv, wg, wo);
    ln_kernel<<<MM/8, 256>>>(x, ln_w, ln_b, w_bias);
    gemm_proj_f16<<<dim3(MM/128, 4), 256, GEMM_SMEM>>>();
    attn_f16<<<dim3(NN, HH), 256, ATTN_SMEM>>>(mask, bg);
    gemm_out_f16<<<dim3(MM/128, 1), 256, GEMM_SMEM>>>(bo, out);
}